// round 8
// baseline (speedup 1.0000x reference)
#include <cuda_runtime.h>
#include <cuda_fp16.h>
#include <stdint.h>

#define N_NODES 150000
#define N_EDGES 3000000
#define D 64
#define D2 (D/2)            // 32 half2/float2 columns per row
#define ROW_I4 8            // fp16 row = 64 halfs = 128B = 8 int4
#define SCAN_B 1024
#define NB ((N_NODES + SCAN_B - 1) / SCAN_B)   // 147 scan blocks

// ---------- device scratch (no allocations allowed) ----------
__device__ __half2 g_sc_a[N_NODES * D2];   // scaled embedding (x * deg), fp16
__device__ __half2 g_sc_b[N_NODES * D2];
__device__ float2  g_acc [N_NODES * D2];   // running layer sum, fp32
__device__ int     g_cnt [N_NODES];        // zero at entry (static init / re-zeroed by spmm3)
__device__ int     g_off [N_NODES + 1];
__device__ int     g_cur [N_NODES];
__device__ int     g_srcs[N_EDGES];
__device__ unsigned long long g_pstate[NB]; // lookback: (sum<<32)|flag

// ---------- launch 0: init (acc=emb, sc_a=half(emb*deg)) + hist + reset lookback ----------
__global__ void k_init_hist(const float2* __restrict__ emb,
                            const float*  __restrict__ deg,
                            const int*    __restrict__ dst) {
    int i = blockIdx.x * blockDim.x + threadIdx.x;
    if (i < N_NODES * D2) {
        int node = i >> 5;
        float d = deg[node];
        float2 v = __ldcs(&emb[i]);
        __stcs(&g_acc[i], v);
        g_sc_a[i] = __floats2half2_rn(v.x * d, v.y * d);
    }
    if (i < N_EDGES) atomicAdd(&g_cnt[dst[i]], 1);
    if (i < NB) g_pstate[i] = 0ULL;
}

// ---------- launch 1: single-pass decoupled-lookback scan ----------
__global__ void k_scan() {
    int b = blockIdx.x, t = threadIdx.x;
    int i = b * SCAN_B + t;
    int v = (i < N_NODES) ? g_cnt[i] : 0;
    int lane = t & 31, wid = t >> 5;

    int incl = v;
    #pragma unroll
    for (int of = 1; of < 32; of <<= 1) {
        int n = __shfl_up_sync(0xffffffffu, incl, of);
        if (lane >= of) incl += n;
    }
    __shared__ int ws[32];
    if (lane == 31) ws[wid] = incl;
    __syncthreads();
    if (wid == 0) {
        int s = ws[lane];
        #pragma unroll
        for (int of = 1; of < 32; of <<= 1) {
            int n = __shfl_up_sync(0xffffffffu, s, of);
            if (lane >= of) s += n;
        }
        ws[lane] = s;
    }
    __syncthreads();
    int block_incl = incl + (wid ? ws[wid - 1] : 0);
    int total = ws[31];

    __shared__ int s_base;
    if (t == 0) {
        if (b == 0) {
            atomicExch(&g_pstate[0], ((unsigned long long)(unsigned)total << 32) | 2ULL);
            s_base = 0;
        } else {
            atomicExch(&g_pstate[b], ((unsigned long long)(unsigned)total << 32) | 1ULL);
            int running = 0;
            for (int p = b - 1; p >= 0; ) {
                unsigned long long st;
                do { st = atomicAdd(&g_pstate[p], 0ULL); } while ((st & 3ULL) == 0ULL);
                running += (int)(unsigned)(st >> 32);
                if ((st & 3ULL) == 2ULL) break;
                p--;
            }
            atomicExch(&g_pstate[b],
                ((unsigned long long)(unsigned)(running + total) << 32) | 2ULL);
            s_base = running;
        }
    }
    __syncthreads();
    int excl = s_base + block_incl - v;
    if (i < N_NODES) { g_off[i] = excl; g_cur[i] = excl; }
    if (i == N_NODES - 1) g_off[N_NODES] = excl + v;
}

// ---------- launch 2: scatter src ids into CSR ----------
__global__ void k_scatter(const int* __restrict__ src, const int* __restrict__ dst) {
    int e = blockIdx.x * blockDim.x + threadIdx.x;
    if (e < N_EDGES) {
        int pos = atomicAdd(&g_cur[dst[e]], 1);
        g_srcs[pos] = src[e];
    }
}

// ---------- launches 3-5: SpMM, warp per dst node, 4 rows per warp LDG.128 ----------
// lane = 8*g + s. Pair-sum in half (HADD2) before H2F convert: ~2.4x fewer
// arithmetic instructions per edge than per-edge convert+fp32-add.
template <int DIR, int LAST>
__global__ void k_spmm(const float* __restrict__ deg,
                       float2*      __restrict__ out) {
    const int4* __restrict__ sc_in =
        (const int4*)((DIR == 0) ? (const void*)g_sc_a : (const void*)g_sc_b);
    __half2*    __restrict__ sc_out = (DIR == 0) ? g_sc_b : g_sc_a;

    int gid  = blockIdx.x * blockDim.x + threadIdx.x;
    int node = gid >> 5;
    int lane = gid & 31;
    if (node >= N_NODES) return;
    unsigned g = lane >> 3;          // edge subgroup 0..3
    unsigned s = lane & 7;           // 16B segment 0..7

    int b = g_off[node];
    int e = g_off[node + 1];
    int cnt = e - b;
    int nfull = cnt & ~7;            // multiple of 8

    float2 acc[4];
    #pragma unroll
    for (int k = 0; k < 4; k++) acc[k] = make_float2(0.f, 0.f);

    // main loop: unpredicated, 8 edges / iteration, 32-bit addressing
    int j = b;
    for (; j < b + nfull; j += 8) {
        unsigned s0 = (unsigned)g_srcs[j + g];
        unsigned s1 = (unsigned)g_srcs[j + 4 + g];
        int4 v0 = sc_in[s0 * ROW_I4 + s];
        int4 v1 = sc_in[s1 * ROW_I4 + s];
        const unsigned* w0 = (const unsigned*)&v0;
        const unsigned* w1 = (const unsigned*)&v1;
        #pragma unroll
        for (int k = 0; k < 4; k++) {
            __half2 h = __hadd2(*(const __half2*)&w0[k], *(const __half2*)&w1[k]);
            float2 f = __half22float2(h);
            acc[k].x += f.x;
            acc[k].y += f.y;
        }
    }
    // tail: one predicated round (up to 7 edges)
    if (nfull != cnt) {
        int j0 = j + (int)g;
        int j1 = j + 4 + (int)g;
        int4 v0 = make_int4(0,0,0,0), v1 = make_int4(0,0,0,0);
        if (j0 < e) v0 = sc_in[(unsigned)g_srcs[j0] * ROW_I4 + s];
        if (j1 < e) v1 = sc_in[(unsigned)g_srcs[j1] * ROW_I4 + s];
        const unsigned* w0 = (const unsigned*)&v0;
        const unsigned* w1 = (const unsigned*)&v1;
        #pragma unroll
        for (int k = 0; k < 4; k++) {
            __half2 h = __hadd2(*(const __half2*)&w0[k], *(const __half2*)&w1[k]);
            float2 f = __half22float2(h);
            acc[k].x += f.x;
            acc[k].y += f.y;
        }
    }

    // reduce across the 4 subgroups (butterfly over lane bits 3,4)
    #pragma unroll
    for (int k = 0; k < 4; k++) {
        acc[k].x += __shfl_xor_sync(0xffffffffu, acc[k].x, 8);
        acc[k].y += __shfl_xor_sync(0xffffffffu, acc[k].y, 8);
        acc[k].x += __shfl_xor_sync(0xffffffffu, acc[k].x, 16);
        acc[k].y += __shfl_xor_sync(0xffffffffu, acc[k].y, 16);
    }

    // epilogue: lane (g,s) owns float2-column c = 4*s + g with value acc[g]
    float d = deg[node];
    unsigned c = (s << 2) + g;
    float vx = acc[g].x * d, vy = acc[g].y * d;

    unsigned o = (unsigned)node * D2 + c;
    float2 a = __ldcs(&g_acc[o]);
    a.x += vx;
    a.y += vy;

    if (LAST) {
        __stcs(&out[o], make_float2(a.x * 0.25f, a.y * 0.25f));
        if (lane == 0) g_cnt[node] = 0;  // reset histogram for next graph replay
    } else {
        __stcs(&g_acc[o], a);
        sc_out[o] = __floats2half2_rn(vx * d, vy * d);
    }
}

// ---------- launch ----------
extern "C" void kernel_launch(void* const* d_in, const int* in_sizes, int n_in,
                              void* d_out, int out_size) {
    const float2* emb = (const float2*)d_in[0];
    const float*  deg = (const float*) d_in[1];
    const int*    src = (const int*)   d_in[2];
    const int*    dst = (const int*)   d_in[3];
    float2*       out = (float2*)      d_out;

    const int TB = 256;

    k_init_hist<<<(N_NODES * D2 + TB - 1) / TB, TB>>>(emb, deg, dst);  // idx 0
    k_scan<<<NB, SCAN_B>>>();                                          // idx 1
    k_scatter<<<(N_EDGES + TB - 1) / TB, TB>>>(src, dst);              // idx 2

    int grid = (N_NODES * 32 + TB - 1) / TB;
    k_spmm<0, 0><<<grid, TB>>>(deg, out);   // idx 3  <- ncu capture slot
    k_spmm<1, 0><<<grid, TB>>>(deg, out);   // idx 4
    k_spmm<0, 1><<<grid, TB>>>(deg, out);   // idx 5
}

// round 9
// speedup vs baseline: 1.2882x; 1.2882x over previous
#include <cuda_runtime.h>
#include <cuda_fp16.h>
#include <stdint.h>

#define N_NODES 150000
#define N_EDGES 3000000
#define D 64
#define D2 (D/2)            // 32 half2/float2 columns per row
#define ROW_I4 8            // fp16 row = 64 halfs = 128B = 8 int4
#define SCAN_B 1024
#define NB ((N_NODES + SCAN_B - 1) / SCAN_B)   // 147 scan blocks

// ---------- device scratch (no allocations allowed) ----------
__device__ __half2 g_sc_a[N_NODES * D2];   // scaled embedding (x * deg), fp16
__device__ __half2 g_sc_b[N_NODES * D2];
__device__ float2  g_acc [N_NODES * D2];   // running layer sum, fp32
__device__ int     g_cnt [N_NODES];        // zero at entry (static init / re-zeroed by spmm3)
__device__ int     g_off [N_NODES + 1];
__device__ int     g_cur [N_NODES];
__device__ int     g_srcs[N_EDGES];
__device__ unsigned long long g_pstate[NB]; // lookback: (sum<<32)|flag

// ---------- launch 0: init (acc=emb, sc_a=half(emb*deg)) + hist + reset lookback ----------
__global__ void k_init_hist(const float2* __restrict__ emb,
                            const float*  __restrict__ deg,
                            const int*    __restrict__ dst) {
    int i = blockIdx.x * blockDim.x + threadIdx.x;
    if (i < N_NODES * D2) {
        int node = i >> 5;
        float d = deg[node];
        float2 v = __ldcs(&emb[i]);
        __stcs(&g_acc[i], v);
        g_sc_a[i] = __floats2half2_rn(v.x * d, v.y * d);
    }
    if (i < N_EDGES) atomicAdd(&g_cnt[dst[i]], 1);
    if (i < NB) g_pstate[i] = 0ULL;
}

// ---------- launch 1: single-pass decoupled-lookback scan ----------
__global__ void k_scan() {
    int b = blockIdx.x, t = threadIdx.x;
    int i = b * SCAN_B + t;
    int v = (i < N_NODES) ? g_cnt[i] : 0;
    int lane = t & 31, wid = t >> 5;

    int incl = v;
    #pragma unroll
    for (int of = 1; of < 32; of <<= 1) {
        int n = __shfl_up_sync(0xffffffffu, incl, of);
        if (lane >= of) incl += n;
    }
    __shared__ int ws[32];
    if (lane == 31) ws[wid] = incl;
    __syncthreads();
    if (wid == 0) {
        int s = ws[lane];
        #pragma unroll
        for (int of = 1; of < 32; of <<= 1) {
            int n = __shfl_up_sync(0xffffffffu, s, of);
            if (lane >= of) s += n;
        }
        ws[lane] = s;
    }
    __syncthreads();
    int block_incl = incl + (wid ? ws[wid - 1] : 0);
    int total = ws[31];

    __shared__ int s_base;
    if (t == 0) {
        if (b == 0) {
            atomicExch(&g_pstate[0], ((unsigned long long)(unsigned)total << 32) | 2ULL);
            s_base = 0;
        } else {
            atomicExch(&g_pstate[b], ((unsigned long long)(unsigned)total << 32) | 1ULL);
            int running = 0;
            for (int p = b - 1; p >= 0; ) {
                unsigned long long st;
                do { st = atomicAdd(&g_pstate[p], 0ULL); } while ((st & 3ULL) == 0ULL);
                running += (int)(unsigned)(st >> 32);
                if ((st & 3ULL) == 2ULL) break;
                p--;
            }
            atomicExch(&g_pstate[b],
                ((unsigned long long)(unsigned)(running + total) << 32) | 2ULL);
            s_base = running;
        }
    }
    __syncthreads();
    int excl = s_base + block_incl - v;
    if (i < N_NODES) { g_off[i] = excl; g_cur[i] = excl; }
    if (i == N_NODES - 1) g_off[N_NODES] = excl + v;
}

// ---------- launch 2: scatter src ids into CSR ----------
__global__ void k_scatter(const int* __restrict__ src, const int* __restrict__ dst) {
    int e = blockIdx.x * blockDim.x + threadIdx.x;
    if (e < N_EDGES) {
        int pos = atomicAdd(&g_cur[dst[e]], 1);
        g_srcs[pos] = src[e];
    }
}

// ---------- launches 3-5: SpMM, warp per dst node, 4 rows per warp LDG.128 ----------
// lane = 8*g + s. Single predicated loop (no tail clone -> low regs) with
// HADD2 pair-sum before H2F convert (half the convert/add stream of R7).
template <int DIR, int LAST>
__global__ void __launch_bounds__(256, 7)
k_spmm(const float* __restrict__ deg,
       float2*      __restrict__ out) {
    const int4* __restrict__ sc_in =
        (const int4*)((DIR == 0) ? (const void*)g_sc_a : (const void*)g_sc_b);
    __half2*    __restrict__ sc_out = (DIR == 0) ? g_sc_b : g_sc_a;

    int gid  = blockIdx.x * blockDim.x + threadIdx.x;
    int node = gid >> 5;
    int lane = gid & 31;
    if (node >= N_NODES) return;
    unsigned g = lane >> 3;          // edge subgroup 0..3
    unsigned s = lane & 7;           // 16B segment 0..7

    int b = g_off[node];
    int e = g_off[node + 1];

    float2 acc[4];
    #pragma unroll
    for (int k = 0; k < 4; k++) acc[k] = make_float2(0.f, 0.f);

    const int4 z4 = make_int4(0, 0, 0, 0);
    // 8 edges / iteration, predicated zero-fill (single codegen of the body)
    for (int j = b; j < e; j += 8) {
        int j0 = j + (int)g;
        int j1 = j + 4 + (int)g;
        int4 v0 = z4, v1 = z4;
        if (j0 < e) v0 = sc_in[(unsigned)g_srcs[j0] * ROW_I4 + s];
        if (j1 < e) v1 = sc_in[(unsigned)g_srcs[j1] * ROW_I4 + s];
        const unsigned* w0 = (const unsigned*)&v0;
        const unsigned* w1 = (const unsigned*)&v1;
        #pragma unroll
        for (int k = 0; k < 4; k++) {
            __half2 h = __hadd2(*(const __half2*)&w0[k], *(const __half2*)&w1[k]);
            float2 f = __half22float2(h);
            acc[k].x += f.x;
            acc[k].y += f.y;
        }
    }

    // reduce across the 4 subgroups (butterfly over lane bits 3,4)
    #pragma unroll
    for (int k = 0; k < 4; k++) {
        acc[k].x += __shfl_xor_sync(0xffffffffu, acc[k].x, 8);
        acc[k].y += __shfl_xor_sync(0xffffffffu, acc[k].y, 8);
        acc[k].x += __shfl_xor_sync(0xffffffffu, acc[k].x, 16);
        acc[k].y += __shfl_xor_sync(0xffffffffu, acc[k].y, 16);
    }

    // epilogue: lane (g,s) owns float2-column c = 4*s + g with value acc[g]
    float d = deg[node];
    unsigned c = (s << 2) + g;
    float vx = acc[g].x * d, vy = acc[g].y * d;

    unsigned o = (unsigned)node * D2 + c;
    float2 a = __ldcs(&g_acc[o]);
    a.x += vx;
    a.y += vy;

    if (LAST) {
        __stcs(&out[o], make_float2(a.x * 0.25f, a.y * 0.25f));
        if (lane == 0) g_cnt[node] = 0;  // reset histogram for next graph replay
    } else {
        __stcs(&g_acc[o], a);
        sc_out[o] = __floats2half2_rn(vx * d, vy * d);
    }
}

// ---------- launch ----------
extern "C" void kernel_launch(void* const* d_in, const int* in_sizes, int n_in,
                              void* d_out, int out_size) {
    const float2* emb = (const float2*)d_in[0];
    const float*  deg = (const float*) d_in[1];
    const int*    src = (const int*)   d_in[2];
    const int*    dst = (const int*)   d_in[3];
    float2*       out = (float2*)      d_out;

    const int TB = 256;

    k_init_hist<<<(N_NODES * D2 + TB - 1) / TB, TB>>>(emb, deg, dst);  // idx 0
    k_scan<<<NB, SCAN_B>>>();                                          // idx 1
    k_scatter<<<(N_EDGES + TB - 1) / TB, TB>>>(src, dst);              // idx 2

    int grid = (N_NODES * 32 + TB - 1) / TB;
    k_spmm<0, 0><<<grid, TB>>>(deg, out);   // idx 3  <- ncu capture slot
    k_spmm<1, 0><<<grid, TB>>>(deg, out);   // idx 4
    k_spmm<0, 1><<<grid, TB>>>(deg, out);   // idx 5
}